// round 16
// baseline (speedup 1.0000x reference)
#include <cuda_runtime.h>
#include <cooperative_groups.h>
#include <cstdint>

namespace cg = cooperative_groups;

#define NB 4
#define NS 8192
#define ND 512
#define NP 32
#define NT (NP + NS)          // 8224
#define LN_EPS 1e-5f
#define ZCH 128               // chunks per batch for reduce (64 rows each)
#define CROWS (NS / ZCH)      // 64
#define KZ 8                  // split-K for GEMVs
#define KS (ND / KZ)          // 64
#define NQ (ND / 4)           // 128 column-quads
#define NGRID 148
#define WCH 257               // write chunks per batch (32 rows each)

// Scratch (device-side only)
__device__ float4 g_part4[ZCH][NB * NQ];  // per-chunk partial x sums
__device__ float4 g_vp4[KZ][NB * NQ];     // split-K vbar partials
__device__ float4 g_yp4[KZ][NB * NQ];     // split-K y partials

__device__ __forceinline__ float4 f4add(float4 a, float4 b) {
    return make_float4(a.x + b.x, a.y + b.y, a.z + b.z, a.w + b.w);
}

// block-wide sum over 512 threads, deterministic
__device__ __forceinline__ float bsum512(float v, float* wred, float* bc) {
    const int t = threadIdx.x, lane = t & 31, wid = t >> 5;
#pragma unroll
    for (int off = 16; off > 0; off >>= 1)
        v += __shfl_xor_sync(0xffffffffu, v, off);
    if (lane == 0) wred[wid] = v;
    __syncthreads();
    if (wid == 0) {
        float s = (lane < 16) ? wred[lane] : 0.f;
#pragma unroll
        for (int off = 8; off > 0; off >>= 1)
            s += __shfl_xor_sync(0xffffffffu, s, off);
        if (lane == 0) *bc = s;
    }
    __syncthreads();
    return *bc;
}

// ---------------------------------------------------------------------------
// Single cooperative kernel, strictly sequential phases:
//  S1: reduce (all blocks) -> g_part4   [R16: loads via __ldcg, L1 bypass]
//  S2: GA: cbar + GEMV1 (32 blocks) -> g_vp4
//  S3: GB: LN + GEMV2   (32 blocks) -> g_yp4
//  S4: W: broadcast     (all blocks, contiguous chunks, st.cs)
// ---------------------------------------------------------------------------
__global__ void __launch_bounds__(512, 1)
titan_fused_kernel(const float4* __restrict__ x4,
                   const float*  __restrict__ pm,
                   const float4* __restrict__ Wv4,
                   const float*  __restrict__ bv,
                   const float*  __restrict__ gamma,
                   const float*  __restrict__ beta,
                   const float4* __restrict__ Wout4,
                   const float4* __restrict__ bout4,
                   float4*       __restrict__ out4) {
    cg::grid_group grid = cg::this_grid();
    const int bid = blockIdx.x, tid = threadIdx.x;

    __shared__ float  spart[8][KS];
    __shared__ float  sk[KS];
    __shared__ float4 sacc[4][NQ];
    __shared__ float  ssn[KS];
    __shared__ float  wred[16], sbc[2];

    // ---------------- S1: reduce x (L2-only loads, no L1 allocation) -------
    {
        const int d4 = tid & 127;
        const int g  = tid >> 7;                 // quarter 0..3
        const int u  = g * NGRID + bid;          // interleaved unit id
        if (u < NB * ZCH) {
            const int b = u >> 7;
            const int z = u & (ZCH - 1);
            const float4* p = x4 + ((size_t)(b * NS + z * CROWS)) * NQ + d4;
            float4 a[4];
#pragma unroll
            for (int j = 0; j < 4; j++) a[j] = make_float4(0.f, 0.f, 0.f, 0.f);
#pragma unroll
            for (int i = 0; i < CROWS; i += 16) {
                float4 v[16];
#pragma unroll
                for (int j = 0; j < 16; j++)
                    v[j] = __ldcg(p + (size_t)(i + j) * NQ);
#pragma unroll
                for (int j = 0; j < 16; j++) {
                    a[j & 3].x += v[j].x;
                    a[j & 3].y += v[j].y;
                    a[j & 3].z += v[j].z;
                    a[j & 3].w += v[j].w;
                }
            }
            float4 r;
            r.x = (a[0].x + a[1].x) + (a[2].x + a[3].x);
            r.y = (a[0].y + a[1].y) + (a[2].y + a[3].y);
            r.z = (a[0].z + a[1].z) + (a[2].z + a[3].z);
            r.w = (a[0].w + a[1].w) + (a[2].w + a[3].w);
            g_part4[z][b * NQ + d4] = r;
        }
    }
    grid.sync();

    // ---------------- S2: GA — cbar slice + GEMV1 partial (32 blocks) ------
    if (bid < NB * KZ) {
        const int b = bid & 3, z = bid >> 2, t = tid;
        {   // cbar slice: 8 groups x 16 chunks (+ pm rows)
            const int kl = t & 63, g = t >> 6;
            const int k  = z * KS + kl;
            const float* gp = (const float*)g_part4 + b * ND + k;
            float a = 0.f;
#pragma unroll
            for (int c = 0; c < ZCH / 8; c++)
                a += gp[(size_t)(g * (ZCH / 8) + c) * (NB * ND)];
#pragma unroll
            for (int p = 0; p < NP / 8; p++)
                a += pm[(g * (NP / 8) + p) * ND + k];
            spart[g][kl] = a;
        }
        __syncthreads();
        if (t < KS) {
            float a = 0.f;
#pragma unroll
            for (int g = 0; g < 8; g++) a += spart[g][t];
            sk[t] = a / (float)NT;
        }
        __syncthreads();
        {   // GEMV1 partial: quad outputs, 4-way k-split
            const int q = t & 127, s = t >> 7;
            const int k0 = z * KS + s * 16;
            float4 acc = make_float4(0.f, 0.f, 0.f, 0.f);
#pragma unroll
            for (int j = 0; j < 16; j++) {
                float4 w = Wv4[(size_t)(k0 + j) * NQ + q];
                float  c = sk[s * 16 + j];
                acc.x += c * w.x; acc.y += c * w.y; acc.z += c * w.z; acc.w += c * w.w;
            }
            sacc[s][q] = acc;
        }
        __syncthreads();
        if (t < NQ) {
            float4 r = f4add(f4add(sacc[0][t], sacc[1][t]),
                             f4add(sacc[2][t], sacc[3][t]));
            g_vp4[z][b * NQ + t] = r;
        }
    }
    grid.sync();

    // ---------------- S3: GB — vbar combine + LN + GEMV2 partial -----------
    if (bid < NB * KZ) {
        const int b = bid & 3, z = bid >> 2, t = tid;
        float vb = bv[t];
#pragma unroll
        for (int c = 0; c < KZ; c++)
            vb += ((const float*)g_vp4[c])[b * ND + t];

        const float mu   = bsum512(vb, wred, &sbc[0]) / (float)ND;
        const float diff = vb - mu;
        const float var  = bsum512(diff * diff, wred, &sbc[1]) / (float)ND;
        const float inv  = rsqrtf(var + LN_EPS);
        const float nrm  = diff * inv * gamma[t] + beta[t];
        __syncthreads();
        if ((t >> 6) == z) ssn[t & 63] = nrm;
        __syncthreads();
        {
            const int q = t & 127, s = t >> 7;
            const int k0 = z * KS + s * 16;
            float4 acc = make_float4(0.f, 0.f, 0.f, 0.f);
#pragma unroll
            for (int j = 0; j < 16; j++) {
                float4 w = Wout4[(size_t)(k0 + j) * NQ + q];
                float  c = ssn[s * 16 + j];
                acc.x += c * w.x; acc.y += c * w.y; acc.z += c * w.z; acc.w += c * w.w;
            }
            sacc[s][q] = acc;
        }
        __syncthreads();
        if (t < NQ) {
            float4 r = f4add(f4add(sacc[0][t], sacc[1][t]),
                             f4add(sacc[2][t], sacc[3][t]));
            g_yp4[z][b * NQ + t] = r;
        }
    }
    grid.sync();

    // ---------------- S4: W — combine y + broadcast (all blocks) -----------
    {
        const int q = tid & 127;
#pragma unroll
        for (int b = 0; b < NB; b++) {
            float4 val = bout4[q];
#pragma unroll
            for (int z = 0; z < KZ; z++)
                val = f4add(val, g_yp4[z][b * NQ + q]);

            // each chunk = 32 rows = 4096 float4; 8 iterations x 512 threads
            for (int c = bid; c < WCH; c += NGRID) {
                float4* o = out4 + (size_t)b * NT * NQ +
                            (size_t)c * (32 * NQ) + tid;
#pragma unroll
                for (int it = 0; it < 8; it++) {
                    asm volatile("st.global.cs.v4.f32 [%0], {%1, %2, %3, %4};"
                                 :: "l"(o + (size_t)it * 512),
                                    "f"(val.x), "f"(val.y), "f"(val.z), "f"(val.w)
                                 : "memory");
                }
            }
        }
    }
}

// ---------------------------------------------------------------------------
extern "C" void kernel_launch(void* const* d_in, const int* in_sizes, int n_in,
                              void* d_out, int out_size) {
    const float4* x4    = (const float4*)d_in[0];
    const float*  pm    = (const float*)d_in[1];
    // d_in[2]=Wk, [3]=bk, [6]=Wq, [7]=bq unused: softmax over zero-state and
    // constant-in-m logits collapse to uniform attention weights.
    const float4* Wv4   = (const float4*)d_in[4];
    const float*  bv    = (const float*)d_in[5];
    const float*  gamma = (const float*)d_in[8];
    const float*  beta  = (const float*)d_in[9];
    const float4* Wout4 = (const float4*)d_in[10];
    const float4* bout4 = (const float4*)d_in[11];
    float4*       out4  = (float4*)d_out;

    void* args[] = { (void*)&x4, (void*)&pm, (void*)&Wv4, (void*)&bv,
                     (void*)&gamma, (void*)&beta, (void*)&Wout4,
                     (void*)&bout4, (void*)&out4 };
    cudaLaunchCooperativeKernel((const void*)titan_fused_kernel,
                                dim3(NGRID), dim3(512), args, 0, 0);
}